// round 5
// baseline (speedup 1.0000x reference)
#include <cuda_runtime.h>
#include <cuda_fp16.h>
#include <stdint.h>

#define IN_C    64
#define OUT_C   128
#define HWID    48
#define IMG     2304          // 48*48
#define IN_DIM  576
#define NROWS   36864         // 16 * 2304
#define KTOT    5184          // 576 silu + 576*8 spline features
#define TM      128           // rows per CTA
#define KC      64            // K per chunk
#define NCHUNK  81
#define NSILU   9             // first 9 chunks are silu features
#define NTC     256           // consumer threads (8 warps)
#define NTP     128           // producer threads (4 warps)
#define NT      (NTC + NTP)
#define STAGES  4
#define STG_B   32768         // 16KB A + 16KB B per stage

static __device__ __align__(16) __half g_Wt[OUT_C * KTOT];

__global__ void prep_weights(const float* __restrict__ Wb,
                             const float* __restrict__ Ws,
                             const float* __restrict__ Sc) {
    int idx = blockIdx.x * 256 + threadIdx.x;
    if (idx >= OUT_C * KTOT) return;
    int o = idx / KTOT;
    int k = idx - o * KTOT;
    float v;
    if (k < IN_DIM) {
        v = Wb[o * IN_DIM + k];
    } else {
        int kk = k - IN_DIM;
        int d = kk >> 3, j = kk & 7;
        v = Ws[(o * IN_DIM + d) * 8 + j] * Sc[o * IN_DIM + d];
    }
    g_Wt[idx] = __float2half(v);
}

// ---------------- helpers ----------------
__device__ __forceinline__ uint32_t smem_u32(const void* p) {
    uint32_t a;
    asm("{ .reg .u64 t; cvta.to.shared.u64 t, %1; cvt.u32.u64 %0, t; }" : "=r"(a) : "l"(p));
    return a;
}
__device__ __forceinline__ uint32_t sw_off(uint32_t o) { return o ^ ((o >> 3) & 0x70u); }

__device__ __forceinline__ void ldmx4(uint32_t r[4], uint32_t a) {
    asm volatile("ldmatrix.sync.aligned.m8n8.x4.shared.b16 {%0,%1,%2,%3}, [%4];"
                 : "=r"(r[0]), "=r"(r[1]), "=r"(r[2]), "=r"(r[3]) : "r"(a));
}
__device__ __forceinline__ void mma16816(float c[4], const uint32_t a[4],
                                         uint32_t b0, uint32_t b1) {
    asm volatile("mma.sync.aligned.m16n8k16.row.col.f32.f16.f16.f32 "
                 "{%0,%1,%2,%3}, {%4,%5,%6,%7}, {%8,%9}, {%0,%1,%2,%3};"
                 : "+f"(c[0]), "+f"(c[1]), "+f"(c[2]), "+f"(c[3])
                 : "r"(a[0]), "r"(a[1]), "r"(a[2]), "r"(a[3]), "r"(b0), "r"(b1));
}
__device__ __forceinline__ void mbar_init(uint32_t a, uint32_t cnt) {
    asm volatile("mbarrier.init.shared.b64 [%0], %1;" :: "r"(a), "r"(cnt) : "memory");
}
__device__ __forceinline__ void mbar_arrive(uint32_t a) {
    asm volatile("mbarrier.arrive.shared.b64 _, [%0];" :: "r"(a) : "memory");
}
__device__ __forceinline__ void mbar_wait(uint32_t a, int parity) {
    asm volatile("{\n\t.reg .pred P;\n\t"
                 "WL_%=:\n\t"
                 "mbarrier.try_wait.parity.acquire.cta.shared::cta.b64 P, [%0], %1, 0x989680;\n\t"
                 "@P bra WD_%=;\n\t"
                 "bra WL_%=;\n\t"
                 "WD_%=:\n\t}"
                 :: "r"(a), "r"(parity) : "memory");
}

// ---------------- main fused warp-specialized HMMA kernel ----------------
__global__ void __launch_bounds__(NT, 1)
convkan_ws(const float* __restrict__ xg, float* __restrict__ outg) {
    extern __shared__ char dsm[];                 // STAGES x [A(16K) | B(16K)]
    __shared__ int s_cb[TM], s_lb[TM], s_khw[TM];
    __shared__ __align__(8) unsigned long long s_bar[2 * STAGES]; // full[0..3], empty[4..7]

    const uint32_t sbase = smem_u32(dsm);
    const uint32_t mb    = smem_u32(s_bar);
    const int tid  = threadIdx.x;
    const int wid  = tid >> 5;
    const int lane = tid & 31;
    const int row_base = blockIdx.x * TM;

    if (tid < TM) {
        int n  = row_base + tid;
        int b  = n / IMG;
        int nl = n - b * IMG;
        int i0 = nl >> 2;
        int c  = i0 / 9;
        int t9 = i0 - c * 9;
        int kh = t9 / 3;
        s_cb[tid]  = (b * IN_C + c) * IMG;
        s_lb[tid]  = (nl & 3) * IN_DIM;
        s_khw[tid] = (kh << 8) | (t9 - kh * 3);
    }
    if (tid == 0) {
        #pragma unroll
        for (int s = 0; s < STAGES; ++s) {
            mbar_init(mb + 8 * s, NTP);                // full: all producer threads
            mbar_init(mb + 8 * (STAGES + s), 8);       // empty: 1 per consumer warp
        }
    }
    __syncthreads();

    if (tid >= NTC) {
        // ===================== PRODUCER (warps 8-11) =====================
        const int ptid = tid - NTC;

        // persistent incremental coords for spline chunks (8 elems/thread)
        int sp_hh[8], sp_w[8];
        #pragma unroll
        for (int it = 0; it < 8; ++it) {
            int e  = ptid + NTP * it;
            int dl = e & 7, m = e >> 3;
            int l0 = s_lb[m] + dl;
            int h  = l0 / HWID;
            sp_w[it]  = l0 - h * HWID;
            sp_hh[it] = h + ((s_khw[m] >> 8) - 1);
        }

        int ps = 0, pph = 1;
        for (int c = 0; c < NCHUNK; ++c) {
            mbar_wait(mb + 8 * (STAGES + ps), pph);
            const uint32_t Ab = sbase + ps * STG_B;
            const uint32_t Bb = Ab + 16384;

            // ---- B tile via cp.async (8 x 16B per thread) ----
            {
                const __half* wsrc = g_Wt + c * KC;
                #pragma unroll
                for (int it = 0; it < 8; ++it) {
                    int s = ptid + NTP * it;
                    int o = s >> 3, seg = s & 7;
                    uint32_t dst = Bb + sw_off((uint32_t)(o * 128 + seg * 16));
                    const void* src = (const void*)(wsrc + (size_t)o * KTOT + seg * 8);
                    asm volatile("cp.async.cg.shared.global [%0], [%1], 16;"
                                 :: "r"(dst), "l"(src));
                }
                asm volatile("cp.async.commit_group;" ::: "memory");
            }

            // ---- A tile: generated fp16 features ----
            if (c < NSILU) {
                const int d0 = c * KC;
                #pragma unroll
                for (int it = 0; it < 4; ++it) {
                    int e = ptid + NTP * it;          // 0..511 runs of 16
                    int g = e & 3, m = e >> 2;
                    int cb   = s_cb[m];
                    int khw  = s_khw[m];
                    int khm1 = (khw >> 8) - 1, kwm1 = (khw & 255) - 1;
                    int l0 = s_lb[m] + d0 + g * 16;
                    int h0 = l0 / HWID;
                    int w0 = l0 - h0 * HWID;
                    uint32_t hv[8];
                    #pragma unroll
                    for (int j = 0; j < 16; j += 2) {
                        float vv[2];
                        #pragma unroll
                        for (int q = 0; q < 2; ++q) {
                            int w = w0 + j + q, h = h0;
                            if (w >= HWID) { w -= HWID; h += 1; }
                            int hh = h + khm1, ww = w + kwm1;
                            float v = 0.f;
                            if (((unsigned)hh < (unsigned)HWID) && ((unsigned)ww < (unsigned)HWID))
                                v = __ldg(xg + cb + hh * HWID + ww);
                            vv[q] = __fdividef(v, 1.f + __expf(-v));
                        }
                        __half2 h2 = __floats2half2_rn(vv[0], vv[1]);
                        hv[j >> 1] = *reinterpret_cast<uint32_t*>(&h2);
                    }
                    uint32_t a0 = Ab + sw_off((uint32_t)(m * 128 + g * 32));
                    uint32_t a1 = Ab + sw_off((uint32_t)(m * 128 + g * 32 + 16));
                    asm volatile("st.shared.v4.b32 [%0], {%1,%2,%3,%4};"
                                 :: "r"(a0), "r"(hv[0]), "r"(hv[1]), "r"(hv[2]), "r"(hv[3]) : "memory");
                    asm volatile("st.shared.v4.b32 [%0], {%1,%2,%3,%4};"
                                 :: "r"(a1), "r"(hv[4]), "r"(hv[5]), "r"(hv[6]), "r"(hv[7]) : "memory");
                }
            } else {
                #pragma unroll
                for (int it = 0; it < 8; ++it) {
                    int e  = ptid + NTP * it;
                    int dl = e & 7, m = e >> 3;
                    int kwm1 = (s_khw[m] & 255) - 1;
                    int hh = sp_hh[it], w = sp_w[it];
                    int ww = w + kwm1;
                    float v = 0.f;
                    if (((unsigned)hh < (unsigned)HWID) && ((unsigned)ww < (unsigned)HWID))
                        v = __ldg(xg + s_cb[m] + hh * HWID + ww);
                    w += 8;
                    if (w >= HWID) { w -= HWID; hh += 1; }
                    sp_w[it] = w; sp_hh[it] = hh;

                    // cardinal cubic B-spline, uniform extended grid (h=0.4, lo=-1)
                    float sv = fmaf(v, 2.5f, 5.5f);
                    float fm = floorf(sv);
                    float f  = sv - fm, f2 = f * f, f3 = f2 * f;
                    float omf = 1.f - f;
                    float q0 = (1.f / 6.f) * omf * omf * omf;
                    float q1 = 0.5f * f3 - f2 + (2.f / 3.f);
                    float q2 = (1.f / 6.f) + 0.5f * (f + f2 - f3);
                    float q3 = (1.f / 6.f) * f3;
                    int t0 = (int)fm - 3;
                    float bj[8];
                    #pragma unroll
                    for (int j = 0; j < 8; ++j) {
                        int i = j - t0;
                        float r = (i == 0) ? q0 : 0.f;
                        r = (i == 1) ? q1 : r;
                        r = (i == 2) ? q2 : r;
                        r = (i == 3) ? q3 : r;
                        bj[j] = r;
                    }
                    __half2 h0 = __floats2half2_rn(bj[0], bj[1]);
                    __half2 h1 = __floats2half2_rn(bj[2], bj[3]);
                    __half2 h2 = __floats2half2_rn(bj[4], bj[5]);
                    __half2 h3 = __floats2half2_rn(bj[6], bj[7]);
                    uint4 seg;
                    seg.x = *(uint32_t*)&h0;
                    seg.y = *(uint32_t*)&h1;
                    seg.z = *(uint32_t*)&h2;
                    seg.w = *(uint32_t*)&h3;
                    uint32_t addr = Ab + sw_off((uint32_t)(m * 128 + dl * 16));
                    asm volatile("st.shared.v4.b32 [%0], {%1,%2,%3,%4};"
                                 :: "r"(addr), "r"(seg.x), "r"(seg.y), "r"(seg.z), "r"(seg.w)
                                 : "memory");
                }
            }
            asm volatile("cp.async.wait_group 0;" ::: "memory");
            mbar_arrive(mb + 8 * ps);          // full[ps]
            if (++ps == STAGES) { ps = 0; pph ^= 1; }
        }
    } else {
        // ===================== CONSUMER (warps 0-7) =====================
        float acc[2][8][4];
        #pragma unroll
        for (int mi = 0; mi < 2; ++mi)
            #pragma unroll
            for (int nb = 0; nb < 8; ++nb)
                #pragma unroll
                for (int q = 0; q < 4; ++q) acc[mi][nb][q] = 0.f;

        const int wm = (wid & 3) * 32;       // warp row base
        const int wn = (wid >> 2) * 64;      // warp col base
        const uint32_t a_row  = wm + (lane & 15);
        const uint32_t a_koff = (lane >> 4) * 16;
        const uint32_t b_row  = wn + ((lane >> 4) << 3) + (lane & 7);
        const uint32_t b_koff = ((lane >> 3) & 1) * 16;

        int cs = 0, cph = 0;
        for (int c = 0; c < NCHUNK; ++c) {
            mbar_wait(mb + 8 * cs, cph);
            const uint32_t aB = sbase + cs * STG_B;
            const uint32_t bB = aB + 16384;
            #pragma unroll
            for (int ks = 0; ks < 4; ++ks) {
                const uint32_t kb = ks * 32;
                uint32_t af[2][4];
                ldmx4(af[0], aB + sw_off(a_row * 128u + kb + a_koff));
                ldmx4(af[1], aB + sw_off((a_row + 16) * 128u + kb + a_koff));
                uint32_t bf[4][4];
                #pragma unroll
                for (int g = 0; g < 4; ++g)
                    ldmx4(bf[g], bB + sw_off((b_row + g * 16) * 128u + kb + b_koff));
                #pragma unroll
                for (int mi = 0; mi < 2; ++mi)
                    #pragma unroll
                    for (int nb = 0; nb < 8; ++nb)
                        mma16816(acc[mi][nb], af[mi],
                                 bf[nb >> 1][(nb & 1) * 2], bf[nb >> 1][(nb & 1) * 2 + 1]);
            }
            if (lane == 0) mbar_arrive(mb + 8 * (STAGES + cs));   // empty[cs]
            if (++cs == STAGES) { cs = 0; cph ^= 1; }
        }

        // epilogue: C[n, o] -> out[n*128 + o] (flat reinterpret of (16,128,48,48))
        #pragma unroll
        for (int mi = 0; mi < 2; ++mi) {
            int r0 = row_base + wm + mi * 16 + (lane >> 2);
            float* p0 = outg + (size_t)r0 * OUT_C + wn + (lane & 3) * 2;
            float* p1 = p0 + 8 * OUT_C;
            #pragma unroll
            for (int nb = 0; nb < 8; ++nb) {
                *(float2*)(p0 + nb * 8) = make_float2(acc[mi][nb][0], acc[mi][nb][1]);
                *(float2*)(p1 + nb * 8) = make_float2(acc[mi][nb][2], acc[mi][nb][3]);
            }
        }
    }
}

extern "C" void kernel_launch(void* const* d_in, const int* in_sizes, int n_in,
                              void* d_out, int out_size) {
    const float* x  = (const float*)d_in[0];   // (16, 64, 48, 48)
    const float* wb = (const float*)d_in[1];   // (128, 576)
    const float* ws = (const float*)d_in[2];   // (128, 576, 8)
    const float* sc = (const float*)d_in[3];   // (128, 576)
    float* out = (float*)d_out;                // flat (36864, 128)

    cudaFuncSetAttribute(convkan_ws, cudaFuncAttributeMaxDynamicSharedMemorySize,
                         STAGES * STG_B);
    prep_weights<<<(OUT_C * KTOT + 255) / 256, 256>>>(wb, ws, sc);
    convkan_ws<<<NROWS / TM, NT, STAGES * STG_B>>>(x, out);
}

// round 6
// speedup vs baseline: 2.1599x; 2.1599x over previous
#include <cuda_runtime.h>
#include <cuda_fp16.h>
#include <stdint.h>

#define IN_C    64
#define OUT_C   128
#define HWID    48
#define IMG     2304          // 48*48
#define IN_DIM  576
#define NROWS   36864         // 16 * 2304
#define KTOT    5184          // 576 silu + 576*8 spline features
#define TM      128           // rows per CTA
#define KC      64            // K per chunk
#define NCHUNK  81
#define NSILU   9             // first 9 chunks are silu features
#define NT      256
#define ABUF    16384         // one stage: 128 x 64 fp16

static __device__ __align__(16) __half g_Wt[OUT_C * KTOT];

// ---------------- weight packing: Wt[o][k], k<576 -> base, else spline*scaler ----
__global__ void prep_weights(const float* __restrict__ Wb,
                             const float* __restrict__ Ws,
                             const float* __restrict__ Sc) {
    int idx = blockIdx.x * 256 + threadIdx.x;
    if (idx >= OUT_C * KTOT) return;
    int o = idx / KTOT;
    int k = idx - o * KTOT;
    float v;
    if (k < IN_DIM) {
        v = Wb[o * IN_DIM + k];
    } else {
        int kk = k - IN_DIM;
        int d = kk >> 3, j = kk & 7;
        v = Ws[(o * IN_DIM + d) * 8 + j] * Sc[o * IN_DIM + d];
    }
    g_Wt[idx] = __float2half(v);
}

// ---------------- helpers ----------------
__device__ __forceinline__ uint32_t smem_u32(const void* p) {
    uint32_t a;
    asm("{ .reg .u64 t; cvta.to.shared.u64 t, %1; cvt.u32.u64 %0, t; }" : "=r"(a) : "l"(p));
    return a;
}
__device__ __forceinline__ uint32_t sw_off(uint32_t o) { return o ^ ((o >> 3) & 0x70u); }

__device__ __forceinline__ void ldmx4(uint32_t r[4], uint32_t a) {
    asm volatile("ldmatrix.sync.aligned.m8n8.x4.shared.b16 {%0,%1,%2,%3}, [%4];"
                 : "=r"(r[0]), "=r"(r[1]), "=r"(r[2]), "=r"(r[3]) : "r"(a));
}
__device__ __forceinline__ void mma16816(float c[4], const uint32_t a[4],
                                         uint32_t b0, uint32_t b1) {
    asm volatile("mma.sync.aligned.m16n8k16.row.col.f32.f16.f16.f32 "
                 "{%0,%1,%2,%3}, {%4,%5,%6,%7}, {%8,%9}, {%0,%1,%2,%3};"
                 : "+f"(c[0]), "+f"(c[1]), "+f"(c[2]), "+f"(c[3])
                 : "r"(a[0]), "r"(a[1]), "r"(a[2]), "r"(a[3]), "r"(b0), "r"(b1));
}

__device__ __forceinline__ void fill_b(uint32_t Bb, int chunk, int tid) {
    const __half* wsrc = g_Wt + chunk * KC;
    #pragma unroll
    for (int it = 0; it < 4; ++it) {
        int s = tid + NT * it;
        int o = s >> 3, seg = s & 7;
        uint32_t dst = Bb + sw_off((uint32_t)(o * 128 + seg * 16));
        const void* src = (const void*)(wsrc + (size_t)o * KTOT + seg * 8);
        asm volatile("cp.async.cg.shared.global [%0], [%1], 16;" :: "r"(dst), "l"(src));
    }
}

// ---------------- main fused HMMA kernel (intra-warp pipelined producer) ----------------
__global__ void __launch_bounds__(NT, 2)
convkan_mma(const float* __restrict__ xg, float* __restrict__ outg) {
    extern __shared__ char dsm[];                 // [A0|A1|B0|B1] 4*16KB
    __shared__ int s_cb[TM], s_lb[TM], s_khw[TM];

    const uint32_t sbase = smem_u32(dsm);
    const uint32_t sB = sbase + 2 * ABUF;
    const int tid  = threadIdx.x;
    const int wid  = tid >> 5;
    const int lane = tid & 31;
    const int row_base = blockIdx.x * TM;

    if (tid < TM) {
        int n  = row_base + tid;
        int b  = n / IMG;
        int nl = n - b * IMG;
        int i0 = nl >> 2;
        int c  = i0 / 9;
        int t9 = i0 - c * 9;
        int kh = t9 / 3;
        s_cb[tid]  = (b * IN_C + c) * IMG;
        s_lb[tid]  = (nl & 3) * IN_DIM;
        s_khw[tid] = (kh << 8) | (t9 - kh * 3);
    }
    __syncthreads();

    // ---- persistent incremental coords for spline chunks (4 elems/thread) ----
    int sp_hh[4], sp_w[4], sp_cb[4], sp_kw[4], sp_maddr[4];
    #pragma unroll
    for (int it = 0; it < 4; ++it) {
        int e  = tid + NT * it;
        int dl = e & 7, m = e >> 3;
        int l0 = s_lb[m] + dl;
        int h  = l0 / HWID;
        sp_w[it]  = l0 - h * HWID;
        sp_hh[it] = h + ((s_khw[m] >> 8) - 1);
        sp_cb[it] = s_cb[m];
        sp_kw[it] = (s_khw[m] & 255) - 1;
        sp_maddr[it] = m * 128 + dl * 16;
    }
    float xv[4];

    // prefetch x values for next spline chunk, advancing persistent coords
    auto prefetch_spline = [&]() {
        #pragma unroll
        for (int it = 0; it < 4; ++it) {
            int hh = sp_hh[it], w = sp_w[it];
            int ww = w + sp_kw[it];
            float v = 0.f;
            if (((unsigned)hh < (unsigned)HWID) && ((unsigned)ww < (unsigned)HWID))
                v = __ldg(xg + sp_cb[it] + hh * HWID + ww);
            xv[it] = v;
            w += 8;
            if (w >= HWID) { w -= HWID; hh += 1; }
            sp_w[it] = w; sp_hh[it] = hh;
        }
    };

    // compute spline features from prefetched xv, store to A buffer
    auto store_spline = [&](uint32_t Abase) {
        #pragma unroll
        for (int it = 0; it < 4; ++it) {
            float v = xv[it];
            // cardinal cubic B-spline, uniform extended grid (h=0.4, lo=-1)
            float sv = fmaf(v, 2.5f, 5.5f);
            float fm = floorf(sv);
            float f  = sv - fm, f2 = f * f, f3 = f2 * f;
            float omf = 1.f - f;
            float q0 = (1.f / 6.f) * omf * omf * omf;
            float q1 = 0.5f * f3 - f2 + (2.f / 3.f);
            float q2 = (1.f / 6.f) + 0.5f * (f + f2 - f3);
            float q3 = (1.f / 6.f) * f3;
            int t0 = (int)fm - 3;
            float bj[8];
            #pragma unroll
            for (int j = 0; j < 8; ++j) {
                int i = j - t0;
                float r = (i == 0) ? q0 : 0.f;
                r = (i == 1) ? q1 : r;
                r = (i == 2) ? q2 : r;
                r = (i == 3) ? q3 : r;
                bj[j] = r;
            }
            __half2 h0 = __floats2half2_rn(bj[0], bj[1]);
            __half2 h1 = __floats2half2_rn(bj[2], bj[3]);
            __half2 h2 = __floats2half2_rn(bj[4], bj[5]);
            __half2 h3 = __floats2half2_rn(bj[6], bj[7]);
            uint32_t addr = Abase + sw_off((uint32_t)sp_maddr[it]);
            asm volatile("st.shared.v4.b32 [%0], {%1,%2,%3,%4};"
                         :: "r"(addr), "r"(*(uint32_t*)&h0), "r"(*(uint32_t*)&h1),
                            "r"(*(uint32_t*)&h2), "r"(*(uint32_t*)&h3) : "memory");
        }
    };

    // silu generator (chunks 0..8): 2 runs of 16 contiguous k per thread
    auto gen_silu = [&](uint32_t Abase, int chunk) {
        const int d0 = chunk * KC;
        #pragma unroll
        for (int it = 0; it < 2; ++it) {
            int e = tid + NT * it;            // 0..511
            int g = e & 3, m = e >> 2;
            int cb   = s_cb[m];
            int khw  = s_khw[m];
            int khm1 = (khw >> 8) - 1, kwm1 = (khw & 255) - 1;
            int l0 = s_lb[m] + d0 + g * 16;
            int h0 = l0 / HWID;
            int w0 = l0 - h0 * HWID;
            uint32_t hv[8];
            #pragma unroll
            for (int j = 0; j < 16; j += 2) {
                float vv[2];
                #pragma unroll
                for (int q = 0; q < 2; ++q) {
                    int w = w0 + j + q, h = h0;
                    if (w >= HWID) { w -= HWID; h += 1; }
                    int hh = h + khm1, ww = w + kwm1;
                    float v = 0.f;
                    if (((unsigned)hh < (unsigned)HWID) && ((unsigned)ww < (unsigned)HWID))
                        v = __ldg(xg + cb + hh * HWID + ww);
                    vv[q] = __fdividef(v, 1.f + __expf(-v));
                }
                __half2 h2 = __floats2half2_rn(vv[0], vv[1]);
                hv[j >> 1] = *reinterpret_cast<uint32_t*>(&h2);
            }
            uint32_t a0 = Abase + sw_off((uint32_t)(m * 128 + g * 32));
            uint32_t a1 = Abase + sw_off((uint32_t)(m * 128 + g * 32 + 16));
            asm volatile("st.shared.v4.b32 [%0], {%1,%2,%3,%4};"
                         :: "r"(a0), "r"(hv[0]), "r"(hv[1]), "r"(hv[2]), "r"(hv[3]) : "memory");
            asm volatile("st.shared.v4.b32 [%0], {%1,%2,%3,%4};"
                         :: "r"(a1), "r"(hv[4]), "r"(hv[5]), "r"(hv[6]), "r"(hv[7]) : "memory");
        }
    };

    // ---- prologue: stage chunk 0 ----
    fill_b(sB, 0, tid);
    asm volatile("cp.async.commit_group;" ::: "memory");
    gen_silu(sbase, 0);

    float acc[2][8][4];
    #pragma unroll
    for (int mi = 0; mi < 2; ++mi)
        #pragma unroll
        for (int nb = 0; nb < 8; ++nb)
            #pragma unroll
            for (int q = 0; q < 4; ++q) acc[mi][nb][q] = 0.f;

    const int wm = (wid & 3) * 32;       // warp row base (4 warps over 128 rows)
    const int wn = (wid >> 2) * 64;      // warp col base (2 warps over 128 cols)
    const uint32_t a_row  = wm + (lane & 15);
    const uint32_t a_koff = (lane >> 4) * 16;
    const uint32_t b_row  = wn + ((lane >> 4) << 3) + (lane & 7);
    const uint32_t b_koff = ((lane >> 3) & 1) * 16;

    for (int c = 0; c < NCHUNK; ++c) {
        const int buf = c & 1;
        const bool havenext = (c + 1 < NCHUNK);
        if (havenext) {
            // stage B(c+1); prefetch x for A(c+1) if spline (LDGs hide under MMA below)
            fill_b(sB + (buf ^ 1) * ABUF, c + 1, tid);
            asm volatile("cp.async.commit_group;" ::: "memory");
            if (c + 1 >= NSILU) prefetch_spline();
            asm volatile("cp.async.wait_group 1;" ::: "memory");
        } else {
            asm volatile("cp.async.wait_group 0;" ::: "memory");
        }
        __syncthreads();   // A(c), B(c) visible to all warps

        const uint32_t aB = sbase + buf * ABUF;
        const uint32_t bB = sB + buf * ABUF;
        #pragma unroll
        for (int ks = 0; ks < 4; ++ks) {
            const uint32_t kb = ks * 32;
            uint32_t af[2][4];
            ldmx4(af[0], aB + sw_off(a_row * 128u + kb + a_koff));
            ldmx4(af[1], aB + sw_off((a_row + 16) * 128u + kb + a_koff));
            uint32_t bf[4][4];
            #pragma unroll
            for (int g = 0; g < 4; ++g)
                ldmx4(bf[g], bB + sw_off((b_row + g * 16) * 128u + kb + b_koff));
            #pragma unroll
            for (int mi = 0; mi < 2; ++mi)
                #pragma unroll
                for (int nb = 0; nb < 8; ++nb)
                    mma16816(acc[mi][nb], af[mi],
                             bf[nb >> 1][(nb & 1) * 2], bf[nb >> 1][(nb & 1) * 2 + 1]);
        }

        // produce A(c+1) into the other buffer (after MMA so LDG latency was hidden)
        if (havenext) {
            if (c + 1 < NSILU) gen_silu(sbase + (buf ^ 1) * ABUF, c + 1);
            else               store_spline(sbase + (buf ^ 1) * ABUF);
        }
        __syncthreads();   // all MMA(c) + A(c+1)/B staging ordered before next iter
    }

    // epilogue: C[n, o] -> out[n*128 + o] (flat reinterpret of (16,128,48,48))
    #pragma unroll
    for (int mi = 0; mi < 2; ++mi) {
        int r0 = row_base + wm + mi * 16 + (lane >> 2);
        float* p0 = outg + (size_t)r0 * OUT_C + wn + (lane & 3) * 2;
        float* p1 = p0 + 8 * OUT_C;
        #pragma unroll
        for (int nb = 0; nb < 8; ++nb) {
            *(float2*)(p0 + nb * 8) = make_float2(acc[mi][nb][0], acc[mi][nb][1]);
            *(float2*)(p1 + nb * 8) = make_float2(acc[mi][nb][2], acc[mi][nb][3]);
        }
    }
}

extern "C" void kernel_launch(void* const* d_in, const int* in_sizes, int n_in,
                              void* d_out, int out_size) {
    const float* x  = (const float*)d_in[0];   // (16, 64, 48, 48)
    const float* wb = (const float*)d_in[1];   // (128, 576)
    const float* ws = (const float*)d_in[2];   // (128, 576, 8)
    const float* sc = (const float*)d_in[3];   // (128, 576)
    float* out = (float*)d_out;                // flat (36864, 128)

    cudaFuncSetAttribute(convkan_mma, cudaFuncAttributeMaxDynamicSharedMemorySize, 4 * ABUF);
    prep_weights<<<(OUT_C * KTOT + 255) / 256, 256>>>(wb, ws, sc);
    convkan_mma<<<NROWS / TM, NT, 4 * ABUF>>>(x, out);
}

// round 7
// speedup vs baseline: 2.5884x; 1.1984x over previous
#include <cuda_runtime.h>
#include <cuda_fp16.h>
#include <stdint.h>

#define IN_C    64
#define OUT_C   128
#define HWID    48
#define IMG     2304          // 48*48
#define IN_DIM  576
#define NROWS   36864         // 16 * 2304
#define KTOT    5184          // 576 silu + 576*8 spline features
#define TM      128           // rows per CTA
#define KC      64            // K per chunk
#define NCHUNK  81
#define NSILU   9             // first 9 chunks are silu features
#define NT      256
#define ABUF    16384         // one stage: 128 x 64 fp16

static __device__ __align__(16) __half g_Wt[OUT_C * KTOT];

// ---------------- weight packing: Wt[o][k], k<576 -> base, else spline*scaler ----
__global__ void prep_weights(const float* __restrict__ Wb,
                             const float* __restrict__ Ws,
                             const float* __restrict__ Sc) {
    int idx = blockIdx.x * 256 + threadIdx.x;
    if (idx >= OUT_C * KTOT) return;
    int o = idx / KTOT;
    int k = idx - o * KTOT;
    float v;
    if (k < IN_DIM) {
        v = Wb[o * IN_DIM + k];
    } else {
        int kk = k - IN_DIM;
        int d = kk >> 3, j = kk & 7;
        v = Ws[(o * IN_DIM + d) * 8 + j] * Sc[o * IN_DIM + d];
    }
    g_Wt[idx] = __float2half(v);
}

// ---------------- helpers ----------------
__device__ __forceinline__ uint32_t smem_u32(const void* p) {
    uint32_t a;
    asm("{ .reg .u64 t; cvta.to.shared.u64 t, %1; cvt.u32.u64 %0, t; }" : "=r"(a) : "l"(p));
    return a;
}
__device__ __forceinline__ uint32_t sw_off(uint32_t o) { return o ^ ((o >> 3) & 0x70u); }

__device__ __forceinline__ void ldmx4(uint32_t r[4], uint32_t a) {
    asm volatile("ldmatrix.sync.aligned.m8n8.x4.shared.b16 {%0,%1,%2,%3}, [%4];"
                 : "=r"(r[0]), "=r"(r[1]), "=r"(r[2]), "=r"(r[3]) : "r"(a));
}
__device__ __forceinline__ void mma16816(float c[4], const uint32_t a[4],
                                         uint32_t b0, uint32_t b1) {
    asm volatile("mma.sync.aligned.m16n8k16.row.col.f32.f16.f16.f32 "
                 "{%0,%1,%2,%3}, {%4,%5,%6,%7}, {%8,%9}, {%0,%1,%2,%3};"
                 : "+f"(c[0]), "+f"(c[1]), "+f"(c[2]), "+f"(c[3])
                 : "r"(a[0]), "r"(a[1]), "r"(a[2]), "r"(a[3]), "r"(b0), "r"(b1));
}

__device__ __forceinline__ void fill_b(uint32_t Bb, int chunk, int tid) {
    const __half* wsrc = g_Wt + chunk * KC;
    #pragma unroll
    for (int it = 0; it < 4; ++it) {
        int s = tid + NT * it;
        int o = s >> 3, seg = s & 7;
        uint32_t dst = Bb + sw_off((uint32_t)(o * 128 + seg * 16));
        const void* src = (const void*)(wsrc + (size_t)o * KTOT + seg * 8);
        asm volatile("cp.async.cg.shared.global [%0], [%1], 16;" :: "r"(dst), "l"(src));
    }
}

// ---------------- main fused HMMA kernel (prefetch + low-ALU scatter producer) ----------------
__global__ void __launch_bounds__(NT, 2)
convkan_mma(const float* __restrict__ xg, float* __restrict__ outg) {
    extern __shared__ char dsm[];                 // [A0|A1|B0|B1] 4*16KB
    __shared__ int s_cb[TM], s_lb[TM], s_khw[TM];

    const uint32_t sbase = smem_u32(dsm);
    const uint32_t sB = sbase + 2 * ABUF;
    const int tid  = threadIdx.x;
    const int wid  = tid >> 5;
    const int lane = tid & 31;
    const int row_base = blockIdx.x * TM;

    if (tid < TM) {
        int n  = row_base + tid;
        int b  = n / IMG;
        int nl = n - b * IMG;
        int i0 = nl >> 2;
        int c  = i0 / 9;
        int t9 = i0 - c * 9;
        int kh = t9 / 3;
        s_cb[tid]  = (b * IN_C + c) * IMG;
        s_lb[tid]  = (nl & 3) * IN_DIM;
        s_khw[tid] = (kh << 8) | (t9 - kh * 3);
    }
    __syncthreads();

    // ---- persistent incremental coords for spline chunks (4 elems/thread) ----
    int sp_hh[4], sp_w[4], sp_cb[4], sp_kw[4], sp_maddr[4];
    #pragma unroll
    for (int it = 0; it < 4; ++it) {
        int e  = tid + NT * it;
        int dl = e & 7, m = e >> 3;
        int l0 = s_lb[m] + dl;
        int h  = l0 / HWID;
        sp_w[it]  = l0 - h * HWID;
        sp_hh[it] = h + ((s_khw[m] >> 8) - 1);
        sp_cb[it] = s_cb[m];
        sp_kw[it] = (s_khw[m] & 255) - 1;
        sp_maddr[it] = m * 128 + dl * 16;
    }
    float xv[4];

    // issue LDGs for next spline chunk's x values, advance coords (no use until store)
    auto prefetch_spline = [&]() {
        #pragma unroll
        for (int it = 0; it < 4; ++it) {
            int hh = sp_hh[it], w = sp_w[it];
            int ww = w + sp_kw[it];
            float v = 0.f;
            if (((unsigned)hh < (unsigned)HWID) && ((unsigned)ww < (unsigned)HWID))
                v = __ldg(xg + sp_cb[it] + hh * HWID + ww);
            xv[it] = v;
            w += 8;
            if (w >= HWID) { w -= HWID; hh += 1; }
            sp_w[it] = w; sp_hh[it] = hh;
        }
    };

    // compute spline bases from prefetched xv; zero-fill + scatter-store (low ALU, R4 path)
    auto store_spline = [&](uint32_t Abase) {
        #pragma unroll
        for (int it = 0; it < 4; ++it) {
            float v = xv[it];
            // cardinal cubic B-spline, uniform extended grid (h=0.4, lo=-1)
            float sv = fmaf(v, 2.5f, 5.5f);
            float fm = floorf(sv);
            float f  = sv - fm, f2 = f * f, f3 = f2 * f;
            float omf = 1.f - f;
            unsigned short q[4];
            q[0] = __half_as_ushort(__float2half_rn((1.f / 6.f) * omf * omf * omf));
            q[1] = __half_as_ushort(__float2half_rn(0.5f * f3 - f2 + (2.f / 3.f)));
            q[2] = __half_as_ushort(__float2half_rn((1.f / 6.f) + 0.5f * (f + f2 - f3)));
            q[3] = __half_as_ushort(__float2half_rn((1.f / 6.f) * f3));
            int t0 = (int)fm - 3;

            uint32_t addr = Abase + sw_off((uint32_t)sp_maddr[it]);
            asm volatile("st.shared.v4.b32 [%0], {%1,%1,%1,%1};"
                         :: "r"(addr), "r"(0u) : "memory");
            #pragma unroll
            for (int i = 0; i < 4; ++i) {
                int j = t0 + i;
                if ((unsigned)j < 8u)
                    asm volatile("st.shared.b16 [%0], %1;"
                                 :: "r"(addr + (uint32_t)(j * 2)), "h"(q[i]) : "memory");
            }
        }
    };

    // silu generator (chunks 0..8): runs of 16 contiguous k, one division per pair
    auto gen_silu = [&](uint32_t Abase, int chunk) {
        const int d0 = chunk * KC;
        #pragma unroll
        for (int it = 0; it < 2; ++it) {
            int e = tid + NT * it;            // 0..511
            int g = e & 3, m = e >> 2;
            int cb   = s_cb[m];
            int khw  = s_khw[m];
            int khm1 = (khw >> 8) - 1, kwm1 = (khw & 255) - 1;
            int l0 = s_lb[m] + d0 + g * 16;
            int h0 = l0 / HWID;
            int w0 = l0 - h0 * HWID;
            uint32_t hv[8];
            #pragma unroll
            for (int j = 0; j < 16; j += 2) {
                float vv[2];
                #pragma unroll
                for (int q = 0; q < 2; ++q) {
                    int w = w0 + j + q, h = h0;
                    if (w >= HWID) { w -= HWID; h += 1; }
                    int hh = h + khm1, ww = w + kwm1;
                    float v = 0.f;
                    if (((unsigned)hh < (unsigned)HWID) && ((unsigned)ww < (unsigned)HWID))
                        v = __ldg(xg + cb + hh * HWID + ww);
                    vv[q] = __fdividef(v, 1.f + __expf(-v));
                }
                __half2 h2 = __floats2half2_rn(vv[0], vv[1]);
                hv[j >> 1] = *reinterpret_cast<uint32_t*>(&h2);
            }
            uint32_t a0 = Abase + sw_off((uint32_t)(m * 128 + g * 32));
            uint32_t a1 = Abase + sw_off((uint32_t)(m * 128 + g * 32 + 16));
            asm volatile("st.shared.v4.b32 [%0], {%1,%2,%3,%4};"
                         :: "r"(a0), "r"(hv[0]), "r"(hv[1]), "r"(hv[2]), "r"(hv[3]) : "memory");
            asm volatile("st.shared.v4.b32 [%0], {%1,%2,%3,%4};"
                         :: "r"(a1), "r"(hv[4]), "r"(hv[5]), "r"(hv[6]), "r"(hv[7]) : "memory");
        }
    };

    // ---- prologue: stage chunk 0 ----
    fill_b(sB, 0, tid);
    asm volatile("cp.async.commit_group;" ::: "memory");
    gen_silu(sbase, 0);

    float acc[2][8][4];
    #pragma unroll
    for (int mi = 0; mi < 2; ++mi)
        #pragma unroll
        for (int nb = 0; nb < 8; ++nb)
            #pragma unroll
            for (int q = 0; q < 4; ++q) acc[mi][nb][q] = 0.f;

    const int wm = (wid & 3) * 32;       // warp row base (4 warps over 128 rows)
    const int wn = (wid >> 2) * 64;      // warp col base (2 warps over 128 cols)
    const uint32_t a_row  = wm + (lane & 15);
    const uint32_t a_koff = (lane >> 4) * 16;
    const uint32_t b_row  = wn + ((lane >> 4) << 3) + (lane & 7);
    const uint32_t b_koff = ((lane >> 3) & 1) * 16;

    for (int c = 0; c < NCHUNK; ++c) {
        const int buf = c & 1;
        const bool havenext = (c + 1 < NCHUNK);
        if (havenext) {
            // stage B(c+1); issue x LDGs for A(c+1) if spline (hide under MMA below)
            fill_b(sB + (buf ^ 1) * ABUF, c + 1, tid);
            asm volatile("cp.async.commit_group;" ::: "memory");
            if (c + 1 >= NSILU) prefetch_spline();
            asm volatile("cp.async.wait_group 1;" ::: "memory");
        } else {
            asm volatile("cp.async.wait_group 0;" ::: "memory");
        }
        __syncthreads();   // A(c), B(c) visible to all warps

        const uint32_t aB = sbase + buf * ABUF;
        const uint32_t bB = sB + buf * ABUF;
        #pragma unroll
        for (int ks = 0; ks < 4; ++ks) {
            const uint32_t kb = ks * 32;
            uint32_t af[2][4];
            ldmx4(af[0], aB + sw_off(a_row * 128u + kb + a_koff));
            ldmx4(af[1], aB + sw_off((a_row + 16) * 128u + kb + a_koff));
            uint32_t bf[4][4];
            #pragma unroll
            for (int g = 0; g < 4; ++g)
                ldmx4(bf[g], bB + sw_off((b_row + g * 16) * 128u + kb + b_koff));
            #pragma unroll
            for (int mi = 0; mi < 2; ++mi)
                #pragma unroll
                for (int nb = 0; nb < 8; ++nb)
                    mma16816(acc[mi][nb], af[mi],
                             bf[nb >> 1][(nb & 1) * 2], bf[nb >> 1][(nb & 1) * 2 + 1]);
        }

        // produce A(c+1) into the other buffer (LDG latency already absorbed by MMA)
        if (havenext) {
            if (c + 1 < NSILU) gen_silu(sbase + (buf ^ 1) * ABUF, c + 1);
            else               store_spline(sbase + (buf ^ 1) * ABUF);
        }
        __syncthreads();   // all MMA(c) reads + A(c+1) writes ordered before next iter
    }

    // epilogue: C[n, o] -> out[n*128 + o] (flat reinterpret of (16,128,48,48))
    #pragma unroll
    for (int mi = 0; mi < 2; ++mi) {
        int r0 = row_base + wm + mi * 16 + (lane >> 2);
        float* p0 = outg + (size_t)r0 * OUT_C + wn + (lane & 3) * 2;
        float* p1 = p0 + 8 * OUT_C;
        #pragma unroll
        for (int nb = 0; nb < 8; ++nb) {
            *(float2*)(p0 + nb * 8) = make_float2(acc[mi][nb][0], acc[mi][nb][1]);
            *(float2*)(p1 + nb * 8) = make_float2(acc[mi][nb][2], acc[mi][nb][3]);
        }
    }
}

extern "C" void kernel_launch(void* const* d_in, const int* in_sizes, int n_in,
                              void* d_out, int out_size) {
    const float* x  = (const float*)d_in[0];   // (16, 64, 48, 48)
    const float* wb = (const float*)d_in[1];   // (128, 576)
    const float* ws = (const float*)d_in[2];   // (128, 576, 8)
    const float* sc = (const float*)d_in[3];   // (128, 576)
    float* out = (float*)d_out;                // flat (36864, 128)

    cudaFuncSetAttribute(convkan_mma, cudaFuncAttributeMaxDynamicSharedMemorySize, 4 * ABUF);
    prep_weights<<<(OUT_C * KTOT + 255) / 256, 256>>>(wb, ws, sc);
    convkan_mma<<<NROWS / TM, NT, 4 * ABUF>>>(x, out);
}